// round 8
// baseline (speedup 1.0000x reference)
#include <cuda_runtime.h>

// Modified Bessel K1(x) on (0.1, 10.1], matching the JAX fp32 A&S reference.
// Math (R7 form, 13 packed ops/pair, rel_err ~2e-5):
//   small(x) = x*( L*P1(s) + Q'(s) ) + r          [x <= 2]
//       s = x^2, r = rcp(x), L = lg2(x)
//   large(x) = ex2( -log2e*x - 0.5*L + G(r) )     [x > 2]
// R8: Blackwell 256-bit vector memory ops (ld/st.global.v8.f32) — one load
// and one store per thread for 8 elements, halving LSU issue slots and
// address ALU vs 2x128-bit (R7 showed alu pipe at 49% was the binder).

typedef unsigned long long ull;

__device__ __forceinline__ ull f2(float lo, float hi) {
    ull d; asm("mov.b64 %0,{%1,%2};" : "=l"(d) : "f"(lo), "f"(hi)); return d;
}
__device__ __forceinline__ ull dup(float c) { return f2(c, c); }
__device__ __forceinline__ void unpack2(ull v, float& lo, float& hi) {
    asm("mov.b64 {%0,%1},%2;" : "=f"(lo), "=f"(hi) : "l"(v));
}
__device__ __forceinline__ ull ffma2(ull a, ull b, ull c) {
    ull d; asm("fma.rn.f32x2 %0,%1,%2,%3;" : "=l"(d) : "l"(a), "l"(b), "l"(c)); return d;
}
__device__ __forceinline__ ull fmul2(ull a, ull b) {
    ull d; asm("mul.rn.f32x2 %0,%1,%2;" : "=l"(d) : "l"(a), "l"(b)); return d;
}
__device__ __forceinline__ float rcpa(float x) {
    float y; asm("rcp.approx.f32 %0,%1;" : "=f"(y) : "f"(x)); return y;
}
__device__ __forceinline__ float lg2a(float x) {
    float y; asm("lg2.approx.f32 %0,%1;" : "=f"(y) : "f"(x)); return y;
}
__device__ __forceinline__ float ex2a(float x) {
    float y; asm("ex2.approx.f32 %0,%1;" : "=f"(y) : "f"(x)); return y;
}

// 256-bit global load/store (sm_100+; LDG.E.256 / STG.E.256)
__device__ __forceinline__ void ldg_cs_v8(const float* p, float* v) {
    asm("ld.global.cs.v8.f32 {%0,%1,%2,%3,%4,%5,%6,%7},[%8];"
        : "=f"(v[0]), "=f"(v[1]), "=f"(v[2]), "=f"(v[3]),
          "=f"(v[4]), "=f"(v[5]), "=f"(v[6]), "=f"(v[7])
        : "l"(p));
}
__device__ __forceinline__ void stg_cs_v8(float* p, const float* v) {
    asm("st.global.cs.v8.f32 [%0],{%1,%2,%3,%4,%5,%6,%7,%8};"
        :: "l"(p),
           "f"(v[0]), "f"(v[1]), "f"(v[2]), "f"(v[3]),
           "f"(v[4]), "f"(v[5]), "f"(v[6]), "f"(v[7])
        : "memory");
}

__device__ __forceinline__ void k1_pair(float x0, float x1, float& y0, float& y1) {
    const ull x = f2(x0, x1);
    const ull r = f2(rcpa(x0), rcpa(x1));
    const ull L = f2(lg2a(x0), lg2a(x1));
    const ull s = fmul2(x, x);

    // P1(s): ln2 * I1_small refolded to s = x^2, economized deg 2
    ull p1 = dup(2.0408281e-3f);
    p1 = ffma2(p1, s, dup(4.2966284e-2f));
    p1 = ffma2(p1, s, dup(0.34665256f));

    // Q'(s) = Q(s) - P1(s); Q = (P2_exact(s) - 1)/s folded to deg 3
    ull q = dup(-8.3601954e-5f);
    q = ffma2(q, s, dup(-4.8562800e-3f));
    q = ffma2(q, s, dup(-8.5032647e-2f));
    q = ffma2(q, s, dup(-0.30804254f));

    // small = x*(L*P1 + Q') + r
    const ull inner = ffma2(L, p1, q);
    const ull small2 = ffma2(x, inner, r);

    // G(r) = log2(P3(r)), cubic fit on [0.099, 0.5]
    ull g = dup(0.077542f);
    g = ffma2(g, r, dup(-0.221725f));
    g = ffma2(g, r, dup(0.534130f));
    g = ffma2(g, r, dup(0.326080f));

    // earg = -log2e*x - 0.5*L + G
    const ull t = ffma2(L, dup(-0.5f), g);
    const ull earg = ffma2(x, dup(-1.44269504f), t);
    float e0, e1; unpack2(earg, e0, e1);

    float s0, s1;
    unpack2(small2, s0, s1);
    y0 = (x0 <= 2.0f) ? s0 : ex2a(e0);
    y1 = (x1 <= 2.0f) ? s1 : ex2a(e1);
}

static constexpr int TPB = 256;
static constexpr int EPT = 8;  // elements per thread (one 256-bit ld/st)

__global__ void __launch_bounds__(TPB, 8) k1_main(const float* __restrict__ in,
                                                  float* __restrict__ out) {
    long long base = (long long)(blockIdx.x) * (TPB * EPT) + (long long)threadIdx.x * EPT;
    float v[EPT], o[EPT];
    ldg_cs_v8(in + base, v);
    k1_pair(v[0], v[1], o[0], o[1]);
    k1_pair(v[2], v[3], o[2], o[3]);
    k1_pair(v[4], v[5], o[4], o[5]);
    k1_pair(v[6], v[7], o[6], o[7]);
    stg_cs_v8(out + base, o);
}

// Generic scalar tail for leftover elements (unused for 8192x8192).
__device__ __forceinline__ float k1_scalar(float x) {
    float r = rcpa(x), L = lg2a(x);
    float s = x * x;
    float p1 = 2.0408281e-3f;
    p1 = fmaf(p1, s, 4.2966284e-2f);
    p1 = fmaf(p1, s, 0.34665256f);
    float q = -8.3601954e-5f;
    q = fmaf(q, s, -4.8562800e-3f);
    q = fmaf(q, s, -8.5032647e-2f);
    q = fmaf(q, s, -0.30804254f);
    float small = fmaf(x, fmaf(L, p1, q), r);
    float g = 0.077542f;
    g = fmaf(g, r, -0.221725f);
    g = fmaf(g, r, 0.534130f);
    g = fmaf(g, r, 0.326080f);
    float large = ex2a(fmaf(x, -1.44269504f, fmaf(L, -0.5f, g)));
    return (x <= 2.0f) ? small : large;
}

__global__ void k1_tail(const float* __restrict__ in, float* __restrict__ out,
                        int start, int n) {
    int i = start + blockIdx.x * blockDim.x + threadIdx.x;
    if (i < n) out[i] = k1_scalar(in[i]);
}

extern "C" void kernel_launch(void* const* d_in, const int* in_sizes, int n_in,
                              void* d_out, int out_size) {
    const float* x = (const float*)d_in[0];
    float* y = (float*)d_out;
    int n = in_sizes[0];

    int elems_per_block = TPB * EPT;                     // 2048 elements
    int full_blocks = n / elems_per_block;
    if (full_blocks > 0) {
        k1_main<<<full_blocks, TPB>>>(x, y);
    }
    int done = full_blocks * elems_per_block;
    int rem = n - done;
    if (rem > 0) {
        int blocks = (rem + 255) / 256;
        k1_tail<<<blocks, 256>>>(x, y, done, n);
    }
}